// round 1
// baseline (speedup 1.0000x reference)
#include <cuda_runtime.h>
#include <cstdint>

#define BB 64
#define TT 4096
#define HH 15
#define EE 15
#define GG 60   /* 4*H */
#define TCH 32

// Scratch (device globals: allocation inside kernel_launch is forbidden)
__device__ float g_xgf[(size_t)TT * BB * GG + 4096];  // fwd gate preacts [t][b][60]
__device__ float g_xgb[(size_t)TT * BB * GG + 4096];  // bwd gate preacts [t'][b][60] (t' = reversed time)
__device__ float g_hsf[(size_t)TT * BB * HH];         // fwd hidden [b][t][15]
__device__ float g_hsb[(size_t)TT * BB * HH];         // bwd hidden, stored un-reversed: [b][t][15]

// Accurate-enough fast activations (ex2/rcp approx: ~2^-22 rel err, far below 1e-3 budget)
__device__ __forceinline__ float fast_sigmoid(float x) {
    float e, r;
    asm("ex2.approx.f32 %0, %1;" : "=f"(e) : "f"(-1.4426950408889634f * x));
    asm("rcp.approx.f32 %0, %1;" : "=f"(r) : "f"(1.0f + e));
    return r;
}
__device__ __forceinline__ float fast_tanh(float x) {
    // tanh(x) = 1 - 2/(1 + e^{2x})
    float e, r;
    asm("ex2.approx.f32 %0, %1;" : "=f"(e) : "f"(2.8853900817779268f * x));
    asm("rcp.approx.f32 %0, %1;" : "=f"(r) : "f"(1.0f + e));
    return fmaf(-2.0f, r, 1.0f);
}

// ---------------------------------------------------------------------------
// Kernel A: embedding gather + x @ W_ih^T + b for both directions.
// Block: 128 threads, handles one batch row b and a chunk of TCH timesteps.
// Backward direction gathers the length-reversed token directly.
// ---------------------------------------------------------------------------
__global__ void gates_kernel(const int* __restrict__ data,
                             const int* __restrict__ lengths,
                             const float* __restrict__ emb,
                             const float* __restrict__ w_ih_f,
                             const float* __restrict__ b_f,
                             const float* __restrict__ w_ih_b,
                             const float* __restrict__ b_b) {
    __shared__ int tok[2][TCH];
    __shared__ float xs[2][TCH][16];

    const int b   = blockIdx.y;
    const int t0  = blockIdx.x * TCH;
    const int tid = threadIdx.x;
    const int L   = lengths[b];

    if (tid < 2 * TCH) {
        int d  = tid / TCH, tl = tid % TCH;
        int tg = t0 + tl;
        int src = (d == 0) ? tg : min(max(L - 1 - tg, 0), TT - 1);
        tok[d][tl] = data[b * TT + src];
    }
    __syncthreads();
    for (int i = tid; i < 2 * TCH * EE; i += blockDim.x) {
        int e  = i % EE;
        int tl = (i / EE) % TCH;
        int d  = i / (EE * TCH);
        xs[d][tl][e] = emb[(size_t)tok[d][tl] * EE + e];
    }
    __syncthreads();

    if (tid < 2 * GG) {
        const int d = tid / GG;
        const int g = tid % GG;
        const float* w = d ? w_ih_b : w_ih_f;
        const float bias = (d ? b_b : b_f)[g];
        float wr[EE];
#pragma unroll
        for (int k = 0; k < EE; k++) wr[k] = w[g * EE + k];
        float* out = d ? g_xgb : g_xgf;
#pragma unroll 4
        for (int tl = 0; tl < TCH; tl++) {
            float a = bias;
#pragma unroll
            for (int k = 0; k < EE; k++) a = fmaf(xs[d][tl][k], wr[k], a);
            out[((size_t)(t0 + tl) * BB + b) * GG + g] = a;
        }
    }
}

// ---------------------------------------------------------------------------
// Kernel B: the sequential LSTM recurrence. 128 blocks x 32 threads.
// blockIdx.x = dir*64 + b. Lane j (j<15) owns hidden unit j; each lane
// computes all 4 gate dots for its unit; h broadcast via shfl.
// Runs only L_b steps (outputs at t >= L are masked by the reference).
// Backward stores at position L-1-t so kernel C reads linearly.
// ---------------------------------------------------------------------------
__global__ void __launch_bounds__(32, 1)
lstm_rec_kernel(const float* __restrict__ h0,
                const float* __restrict__ c0,
                const float* __restrict__ w_hh_f,
                const float* __restrict__ w_hh_b,
                const int* __restrict__ lengths) {
    const int b    = blockIdx.x & (BB - 1);
    const int dir  = blockIdx.x >> 6;
    const int lane = threadIdx.x;
    const int j    = (lane < HH) ? lane : 0;  // lanes 15..31 shadow lane 0 (never sourced)

    const float* whh = dir ? w_hh_b : w_hh_f;
    const float* xg  = dir ? g_xgb : g_xgf;
    float*       hs  = dir ? g_hsb : g_hsf;
    const int L = lengths[b];

    float wi[HH], wf[HH], wg[HH], wo[HH];
#pragma unroll
    for (int k = 0; k < HH; k++) {
        wi[k] = whh[(j) * HH + k];
        wf[k] = whh[(HH + j) * HH + k];
        wg[k] = whh[(2 * HH + j) * HH + k];
        wo[k] = whh[(3 * HH + j) * HH + k];
    }

    float hj = h0[((size_t)dir * BB + b) * HH + j];
    float c  = c0[((size_t)dir * BB + b) * HH + j];

    const float* xgp = xg + (size_t)b * GG;
    float p0 = xgp[j], p1 = xgp[HH + j], p2 = xgp[2 * HH + j], p3 = xgp[3 * HH + j];

    for (int t = 0; t < L; t++) {
        float ai = p0, af = p1, ag = p2, ao = p3;
        // prefetch next timestep's preactivations (array padded past t = T)
        const float* nx = xgp + (size_t)(t + 1) * BB * GG;
        p0 = nx[j]; p1 = nx[HH + j]; p2 = nx[2 * HH + j]; p3 = nx[3 * HH + j];

#pragma unroll
        for (int k = 0; k < HH; k++) {
            float hk = __shfl_sync(0xffffffffu, hj, k);
            ai = fmaf(hk, wi[k], ai);
            af = fmaf(hk, wf[k], af);
            ag = fmaf(hk, wg[k], ag);
            ao = fmaf(hk, wo[k], ao);
        }

        float ig = fast_sigmoid(ai);
        float fg = fast_sigmoid(af);
        float og = fast_sigmoid(ao);
        float gg = fast_tanh(ag);
        c = fmaf(fg, c, ig * gg);
        hj = og * fast_tanh(c);

        if (lane < HH) {
            int tpos = dir ? (L - 1 - t) : t;
            hs[((size_t)b * TT + tpos) * HH + j] = hj;
        }
    }
}

// ---------------------------------------------------------------------------
// Kernel C: out[b,t,:] = valid ? [hf|hb] @ lin_w^T + lin_b : lin_b
// One thread per (b,t). lin_w staged in smem (rows padded to 32 for float4 LDS).
// ---------------------------------------------------------------------------
__global__ void out_kernel(const float* __restrict__ lin_w,
                           const float* __restrict__ lin_b,
                           const int* __restrict__ lengths,
                           float* __restrict__ out) {
    __shared__ __align__(16) float sw[45 * 32];
    __shared__ float sb[45];
    const int tid = threadIdx.x;
    for (int i = tid; i < 45 * 32; i += blockDim.x) {
        int o = i >> 5, k = i & 31;
        sw[i] = (k < 30) ? lin_w[o * 30 + k] : 0.0f;
    }
    if (tid < 45) sb[tid] = lin_b[tid];
    __syncthreads();

    const int idx = blockIdx.x * blockDim.x + tid;
    if (idx >= BB * TT) return;
    const int b = idx >> 12;
    const int t = idx & (TT - 1);

    float hx[32];
#pragma unroll
    for (int k = 0; k < 32; k++) hx[k] = 0.0f;
    if (t < lengths[b]) {
#pragma unroll
        for (int k = 0; k < HH; k++) {
            hx[k]      = g_hsf[(size_t)idx * HH + k];
            hx[15 + k] = g_hsb[(size_t)idx * HH + k];
        }
    }

    float* op = out + (size_t)idx * 45;
#pragma unroll
    for (int o = 0; o < 45; o++) {
        float a = sb[o];
#pragma unroll
        for (int q = 0; q < 8; q++) {
            float4 w4 = *reinterpret_cast<const float4*>(&sw[o * 32 + q * 4]);
            a = fmaf(hx[q * 4 + 0], w4.x, a);
            a = fmaf(hx[q * 4 + 1], w4.y, a);
            a = fmaf(hx[q * 4 + 2], w4.z, a);
            a = fmaf(hx[q * 4 + 3], w4.w, a);
        }
        op[o] = a;
    }
}

// ---------------------------------------------------------------------------
extern "C" void kernel_launch(void* const* d_in, const int* in_sizes, int n_in,
                              void* d_out, int out_size) {
    // Inputs in setup_inputs order. innerSize is a scalar that may or may not
    // be materialized as an input tensor; detect via count.
    int off = (n_in >= 14) ? 1 : 0;
    const int*   data    = (const int*)d_in[0];
    const int*   lengths = (const int*)d_in[1 + off];
    const float* emb     = (const float*)d_in[2 + off];
    const float* h0      = (const float*)d_in[3 + off];
    const float* c0      = (const float*)d_in[4 + off];
    const float* w_ih_f  = (const float*)d_in[5 + off];
    const float* w_hh_f  = (const float*)d_in[6 + off];
    const float* b_f     = (const float*)d_in[7 + off];
    const float* w_ih_b  = (const float*)d_in[8 + off];
    const float* w_hh_b  = (const float*)d_in[9 + off];
    const float* b_b     = (const float*)d_in[10 + off];
    const float* lin_w   = (const float*)d_in[11 + off];
    const float* lin_b   = (const float*)d_in[12 + off];
    float* out = (float*)d_out;

    gates_kernel<<<dim3(TT / TCH, BB), 128>>>(data, lengths, emb, w_ih_f, b_f, w_ih_b, b_b);
    lstm_rec_kernel<<<2 * BB, 32>>>(h0, c0, w_hh_f, w_hh_b, lengths);
    out_kernel<<<(BB * TT + 127) / 128, 128>>>(lin_w, lin_b, lengths, out);
}

// round 2
// speedup vs baseline: 1.9261x; 1.9261x over previous
#include <cuda_runtime.h>
#include <cstdint>

#define BB 64
#define TT 4096
#define HH 15
#define EE 15
#define GG 60   /* 4*H */
#define TCH 32
#define UU 8    /* prefetch depth (steps) in the recurrence */

// Scratch (device globals: allocation inside kernel_launch is forbidden).
// Padding of 2*UU*BB*GG floats past t=TT so deep prefetch over-reads land in
// zero-initialized memory (those steps' results are never stored).
#define PADF (2 * UU * BB * GG)
__device__ float g_xgf[(size_t)TT * BB * GG + PADF];  // fwd gate preacts [t][b][60]
__device__ float g_xgb[(size_t)TT * BB * GG + PADF];  // bwd gate preacts [t'][b][60]
__device__ float g_hsf[(size_t)TT * BB * HH];         // fwd hidden [b][t][15]
__device__ float g_hsb[(size_t)TT * BB * HH];         // bwd hidden, stored un-reversed

// Accurate-enough fast activations (ex2/rcp approx: ~2^-22 rel err)
__device__ __forceinline__ float fast_sigmoid(float x) {
    float e, r;
    asm("ex2.approx.f32 %0, %1;" : "=f"(e) : "f"(-1.4426950408889634f * x));
    asm("rcp.approx.f32 %0, %1;" : "=f"(r) : "f"(1.0f + e));
    return r;
}
__device__ __forceinline__ float fast_tanh(float x) {
    float e, r;
    asm("ex2.approx.f32 %0, %1;" : "=f"(e) : "f"(2.8853900817779268f * x));
    asm("rcp.approx.f32 %0, %1;" : "=f"(r) : "f"(1.0f + e));
    return fmaf(-2.0f, r, 1.0f);
}

// ---------------------------------------------------------------------------
// Kernel A: embedding gather + x @ W_ih^T + b for both directions.
// ---------------------------------------------------------------------------
__global__ void gates_kernel(const int* __restrict__ data,
                             const int* __restrict__ lengths,
                             const float* __restrict__ emb,
                             const float* __restrict__ w_ih_f,
                             const float* __restrict__ b_f,
                             const float* __restrict__ w_ih_b,
                             const float* __restrict__ b_b) {
    __shared__ int tok[2][TCH];
    __shared__ float xs[2][TCH][16];

    const int b   = blockIdx.y;
    const int t0  = blockIdx.x * TCH;
    const int tid = threadIdx.x;
    const int L   = lengths[b];

    if (tid < 2 * TCH) {
        int d  = tid / TCH, tl = tid % TCH;
        int tg = t0 + tl;
        int src = (d == 0) ? tg : min(max(L - 1 - tg, 0), TT - 1);
        tok[d][tl] = data[b * TT + src];
    }
    __syncthreads();
    for (int i = tid; i < 2 * TCH * EE; i += blockDim.x) {
        int e  = i % EE;
        int tl = (i / EE) % TCH;
        int d  = i / (EE * TCH);
        xs[d][tl][e] = emb[(size_t)tok[d][tl] * EE + e];
    }
    __syncthreads();

    if (tid < 2 * GG) {
        const int d = tid / GG;
        const int g = tid % GG;
        const float* w = d ? w_ih_b : w_ih_f;
        const float bias = (d ? b_b : b_f)[g];
        float wr[EE];
#pragma unroll
        for (int k = 0; k < EE; k++) wr[k] = w[g * EE + k];
        float* out = d ? g_xgb : g_xgf;
#pragma unroll 4
        for (int tl = 0; tl < TCH; tl++) {
            float a = bias;
#pragma unroll
            for (int k = 0; k < EE; k++) a = fmaf(xs[d][tl][k], wr[k], a);
            out[((size_t)(t0 + tl) * BB + b) * GG + g] = a;
        }
    }
}

// ---------------------------------------------------------------------------
// Kernel B: sequential LSTM recurrence, 128 warps (one per dir x batch).
// Deep software pipeline: circular register buffer holding UU steps of gate
// preactivations; load for step t+u+UU issued as buf[u] is consumed, covering
// ~600cy DRAM latency with ~8 steps (~1400cy) of independent compute.
// ---------------------------------------------------------------------------
__global__ void __launch_bounds__(32, 1)
lstm_rec_kernel(const float* __restrict__ h0,
                const float* __restrict__ c0,
                const float* __restrict__ w_hh_f,
                const float* __restrict__ w_hh_b,
                const int* __restrict__ lengths) {
    const int b    = blockIdx.x & (BB - 1);
    const int dir  = blockIdx.x >> 6;
    const int lane = threadIdx.x;
    const int j    = (lane < HH) ? lane : 0;  // lanes 15..31 shadow lane 0
    const bool wr_en = (lane < HH);

    const float* whh = dir ? w_hh_b : w_hh_f;
    const float* xg  = dir ? g_xgb : g_xgf;
    float*       hs  = dir ? g_hsb : g_hsf;
    const int L = lengths[b];

    float wi[HH], wf[HH], wg[HH], wo[HH];
#pragma unroll
    for (int k = 0; k < HH; k++) {
        wi[k] = whh[(j) * HH + k];
        wf[k] = whh[(HH + j) * HH + k];
        wg[k] = whh[(2 * HH + j) * HH + k];
        wo[k] = whh[(3 * HH + j) * HH + k];
    }

    float hj = h0[((size_t)dir * BB + b) * HH + j];
    float c  = c0[((size_t)dir * BB + b) * HH + j];

    const float* xgp = xg + (size_t)b * GG;
    const size_t stride = (size_t)BB * GG;

    // Prologue: fill circular buffer with steps 0..UU-1
    float p0[UU], p1[UU], p2[UU], p3[UU];
#pragma unroll
    for (int u = 0; u < UU; u++) {
        const float* s = xgp + (size_t)u * stride;
        p0[u] = s[j]; p1[u] = s[HH + j]; p2[u] = s[2 * HH + j]; p3[u] = s[3 * HH + j];
    }

    for (int t = 0; t < L; t += UU) {
#pragma unroll
        for (int u = 0; u < UU; u++) {
            float ai = p0[u], af = p1[u], ag = p2[u], ao = p3[u];
            // refill slot u with step t+u+UU (over-reads hit zero padding)
            const float* nx = xgp + (size_t)(t + u + UU) * stride;
            p0[u] = nx[j]; p1[u] = nx[HH + j]; p2[u] = nx[2 * HH + j]; p3[u] = nx[3 * HH + j];

#pragma unroll
            for (int k = 0; k < HH; k++) {
                float hk = __shfl_sync(0xffffffffu, hj, k);
                ai = fmaf(hk, wi[k], ai);
                af = fmaf(hk, wf[k], af);
                ag = fmaf(hk, wg[k], ag);
                ao = fmaf(hk, wo[k], ao);
            }

            float ig = fast_sigmoid(ai);
            float fg = fast_sigmoid(af);
            float og = fast_sigmoid(ao);
            float gg = fast_tanh(ag);
            c = fmaf(fg, c, ig * gg);
            hj = og * fast_tanh(c);

            int tt = t + u;
            if (wr_en && tt < L) {
                int tpos = dir ? (L - 1 - tt) : tt;
                hs[((size_t)b * TT + tpos) * HH + j] = hj;
            }
        }
    }
}

// ---------------------------------------------------------------------------
// Kernel C: out[b,t,:] = valid ? [hf|hb] @ lin_w^T + lin_b : lin_b
// ---------------------------------------------------------------------------
__global__ void out_kernel(const float* __restrict__ lin_w,
                           const float* __restrict__ lin_b,
                           const int* __restrict__ lengths,
                           float* __restrict__ out) {
    __shared__ __align__(16) float sw[45 * 32];
    __shared__ float sb[45];
    const int tid = threadIdx.x;
    for (int i = tid; i < 45 * 32; i += blockDim.x) {
        int o = i >> 5, k = i & 31;
        sw[i] = (k < 30) ? lin_w[o * 30 + k] : 0.0f;
    }
    if (tid < 45) sb[tid] = lin_b[tid];
    __syncthreads();

    const int idx = blockIdx.x * blockDim.x + tid;
    if (idx >= BB * TT) return;
    const int b = idx >> 12;
    const int t = idx & (TT - 1);

    float hx[32];
#pragma unroll
    for (int k = 0; k < 32; k++) hx[k] = 0.0f;
    if (t < lengths[b]) {
#pragma unroll
        for (int k = 0; k < HH; k++) {
            hx[k]      = g_hsf[(size_t)idx * HH + k];
            hx[15 + k] = g_hsb[(size_t)idx * HH + k];
        }
    }

    float* op = out + (size_t)idx * 45;
#pragma unroll
    for (int o = 0; o < 45; o++) {
        float a = sb[o];
#pragma unroll
        for (int q = 0; q < 8; q++) {
            float4 w4 = *reinterpret_cast<const float4*>(&sw[o * 32 + q * 4]);
            a = fmaf(hx[q * 4 + 0], w4.x, a);
            a = fmaf(hx[q * 4 + 1], w4.y, a);
            a = fmaf(hx[q * 4 + 2], w4.z, a);
            a = fmaf(hx[q * 4 + 3], w4.w, a);
        }
        op[o] = a;
    }
}

// ---------------------------------------------------------------------------
extern "C" void kernel_launch(void* const* d_in, const int* in_sizes, int n_in,
                              void* d_out, int out_size) {
    int off = (n_in >= 14) ? 1 : 0;
    const int*   data    = (const int*)d_in[0];
    const int*   lengths = (const int*)d_in[1 + off];
    const float* emb     = (const float*)d_in[2 + off];
    const float* h0      = (const float*)d_in[3 + off];
    const float* c0      = (const float*)d_in[4 + off];
    const float* w_ih_f  = (const float*)d_in[5 + off];
    const float* w_hh_f  = (const float*)d_in[6 + off];
    const float* b_f     = (const float*)d_in[7 + off];
    const float* w_ih_b  = (const float*)d_in[8 + off];
    const float* w_hh_b  = (const float*)d_in[9 + off];
    const float* b_b     = (const float*)d_in[10 + off];
    const float* lin_w   = (const float*)d_in[11 + off];
    const float* lin_b   = (const float*)d_in[12 + off];
    float* out = (float*)d_out;

    gates_kernel<<<dim3(TT / TCH, BB), 128>>>(data, lengths, emb, w_ih_f, b_f, w_ih_b, b_b);
    lstm_rec_kernel<<<2 * BB, 32>>>(h0, c0, w_hh_f, w_hh_b, lengths);
    out_kernel<<<(BB * TT + 127) / 128, 128>>>(lin_w, lin_b, lengths, out);
}

// round 3
// speedup vs baseline: 2.5233x; 1.3101x over previous
#include <cuda_runtime.h>
#include <cstdint>

#define BB 64
#define TT 4096
#define HH 15
#define EE 15
#define GG 60   /* 4*H */
#define TCH 32
#define UU 8    /* prefetch depth (steps) in the recurrence */

// Gate preacts stored as float4 {i,f,g,o} per (t,b,unit): one LDG.128/step.
// Padding of 2*UU steps past t=TT so deep prefetch over-reads are in-bounds.
__device__ float4 g_xgf[(size_t)TT * BB * HH + 2 * UU * BB * HH];
__device__ float4 g_xgb[(size_t)TT * BB * HH + 2 * UU * BB * HH];
__device__ float  g_hsf[(size_t)TT * BB * HH];   // fwd hidden [b][t][15]
__device__ float  g_hsb[(size_t)TT * BB * HH];   // bwd hidden, un-reversed

typedef unsigned long long ull;

__device__ __forceinline__ ull pack2(float lo, float hi) {
    ull r; asm("mov.b64 %0, {%1,%2};" : "=l"(r) : "f"(lo), "f"(hi)); return r;
}
__device__ __forceinline__ void unpack2(float& lo, float& hi, ull v) {
    asm("mov.b64 {%0,%1}, %2;" : "=f"(lo), "=f"(hi) : "l"(v));
}
__device__ __forceinline__ ull fma2(ull a, ull b, ull c) {
    ull d; asm("fma.rn.f32x2 %0, %1, %2, %3;" : "=l"(d) : "l"(a), "l"(b), "l"(c)); return d;
}
__device__ __forceinline__ ull add2(ull a, ull b) {
    ull d; asm("add.rn.f32x2 %0, %1, %2;" : "=l"(d) : "l"(a), "l"(b)); return d;
}
__device__ __forceinline__ float tanh_t(float x) {
    float t; asm("tanh.approx.f32 %0, %1;" : "=f"(t) : "f"(x)); return t;
}
__device__ __forceinline__ float sig_t(float x) {
    float t; asm("tanh.approx.f32 %0, %1;" : "=f"(t) : "f"(0.5f * x));
    return fmaf(0.5f, t, 0.5f);
}

// ---------------------------------------------------------------------------
// Kernel A: embedding gather + x @ W_ih^T + b, writing [t][b][j][gate] float4s.
// ---------------------------------------------------------------------------
__global__ void gates_kernel(const int* __restrict__ data,
                             const int* __restrict__ lengths,
                             const float* __restrict__ emb,
                             const float* __restrict__ w_ih_f,
                             const float* __restrict__ b_f,
                             const float* __restrict__ w_ih_b,
                             const float* __restrict__ b_b) {
    __shared__ int tok[2][TCH];
    __shared__ float xs[2][TCH][16];

    const int b   = blockIdx.y;
    const int t0  = blockIdx.x * TCH;
    const int tid = threadIdx.x;
    const int L   = lengths[b];

    if (tid < 2 * TCH) {
        int d  = tid / TCH, tl = tid % TCH;
        int tg = t0 + tl;
        int src = (d == 0) ? tg : min(max(L - 1 - tg, 0), TT - 1);
        tok[d][tl] = data[b * TT + src];
    }
    __syncthreads();
    for (int i = tid; i < 2 * TCH * EE; i += blockDim.x) {
        int e  = i % EE;
        int tl = (i / EE) % TCH;
        int d  = i / (EE * TCH);
        xs[d][tl][e] = emb[(size_t)tok[d][tl] * EE + e];
    }
    __syncthreads();

    if (tid < 2 * GG) {
        const int d    = tid / GG;
        const int g    = tid % GG;
        const int gate = g / HH;       // 0..3 (i,f,g,o)
        const int j    = g % HH;       // unit
        const float* w = d ? w_ih_b : w_ih_f;
        const float bias = (d ? b_b : b_f)[g];
        float wr[EE];
#pragma unroll
        for (int k = 0; k < EE; k++) wr[k] = w[g * EE + k];
        float* out = (float*)(d ? g_xgb : g_xgf);
#pragma unroll 4
        for (int tl = 0; tl < TCH; tl++) {
            float a = bias;
#pragma unroll
            for (int k = 0; k < EE; k++) a = fmaf(xs[d][tl][k], wr[k], a);
            out[(((size_t)(t0 + tl) * BB + b) * HH + j) * 4 + gate] = a;
        }
    }
}

// ---------------------------------------------------------------------------
// Kernel B: sequential LSTM recurrence. One warp per (dir, batch).
// Lane j owns unit j. Packed f32x2 dots ({i,f} and {g,o} pairs), split
// accumulators, MUFU.TANH activations, float4 gate loads, depth-8 prefetch.
// ---------------------------------------------------------------------------
__global__ void __launch_bounds__(32, 1)
lstm_rec_kernel(const float* __restrict__ h0,
                const float* __restrict__ c0,
                const float* __restrict__ w_hh_f,
                const float* __restrict__ w_hh_b,
                const int* __restrict__ lengths) {
    const int b    = blockIdx.x & (BB - 1);
    const int dir  = blockIdx.x >> 6;
    const int lane = threadIdx.x;
    const int j    = (lane < HH) ? lane : 0;
    const bool wr_en = (lane < HH);

    const float*  whh = dir ? w_hh_b : w_hh_f;
    const float4* xg  = dir ? g_xgb : g_xgf;
    float*        hs  = dir ? g_hsb : g_hsf;
    const int L = lengths[b];

    // Pack recurrent weights: wif[k] = {W_i[j][k], W_f[j][k]}, wgo likewise.
    ull wif[HH], wgo[HH];
#pragma unroll
    for (int k = 0; k < HH; k++) {
        wif[k] = pack2(whh[(j) * HH + k],      whh[(HH + j) * HH + k]);
        wgo[k] = pack2(whh[(2 * HH + j) * HH + k], whh[(3 * HH + j) * HH + k]);
    }

    float hj = h0[((size_t)dir * BB + b) * HH + j];
    float c  = c0[((size_t)dir * BB + b) * HH + j];

    const size_t BHH = (size_t)BB * HH;
    const float4* xgp = xg + (size_t)b * HH + j;

    // Prologue: fill circular buffer with steps 0..UU-1
    float4 pf[UU];
#pragma unroll
    for (int u = 0; u < UU; u++) pf[u] = xgp[(size_t)u * BHH];

    for (int t = 0; t < L; t += UU) {
#pragma unroll
        for (int u = 0; u < UU; u++) {
            float4 pv = pf[u];
            pf[u] = xgp[(size_t)(t + u + UU) * BHH];   // refill (padding-safe)

            ull aA0 = pack2(pv.x, pv.y), aA1 = 0;      // {i,f} partial chains
            ull aB0 = pack2(pv.z, pv.w), aB1 = 0;      // {g,o} partial chains
#pragma unroll
            for (int k = 0; k < HH; k++) {
                float hk = __shfl_sync(0xffffffffu, hj, k);
                ull h2 = pack2(hk, hk);
                if (k < 8) { aA0 = fma2(h2, wif[k], aA0); aB0 = fma2(h2, wgo[k], aB0); }
                else       { aA1 = fma2(h2, wif[k], aA1); aB1 = fma2(h2, wgo[k], aB1); }
            }
            ull aA = add2(aA0, aA1);
            ull aB = add2(aB0, aB1);
            float ai, af, ag, ao;
            unpack2(ai, af, aA);
            unpack2(ag, ao, aB);

            float ig = sig_t(ai);
            float fg = sig_t(af);
            float og = sig_t(ao);
            float gg = tanh_t(ag);
            c  = fmaf(fg, c, ig * gg);
            hj = og * tanh_t(c);

            int tt = t + u;
            if (wr_en && tt < L) {
                int tpos = dir ? (L - 1 - tt) : tt;
                hs[((size_t)b * TT + tpos) * HH + j] = hj;
            }
        }
    }
}

// ---------------------------------------------------------------------------
// Kernel C: out[b,t,:] = valid ? [hf|hb] @ lin_w^T + lin_b : lin_b
// ---------------------------------------------------------------------------
__global__ void out_kernel(const float* __restrict__ lin_w,
                           const float* __restrict__ lin_b,
                           const int* __restrict__ lengths,
                           float* __restrict__ out) {
    __shared__ __align__(16) float sw[45 * 32];
    __shared__ float sb[45];
    const int tid = threadIdx.x;
    for (int i = tid; i < 45 * 32; i += blockDim.x) {
        int o = i >> 5, k = i & 31;
        sw[i] = (k < 30) ? lin_w[o * 30 + k] : 0.0f;
    }
    if (tid < 45) sb[tid] = lin_b[tid];
    __syncthreads();

    const int idx = blockIdx.x * blockDim.x + tid;
    if (idx >= BB * TT) return;
    const int b = idx >> 12;
    const int t = idx & (TT - 1);

    float hx[32];
#pragma unroll
    for (int k = 0; k < 32; k++) hx[k] = 0.0f;
    if (t < lengths[b]) {
#pragma unroll
        for (int k = 0; k < HH; k++) {
            hx[k]      = g_hsf[(size_t)idx * HH + k];
            hx[15 + k] = g_hsb[(size_t)idx * HH + k];
        }
    }

    float* op = out + (size_t)idx * 45;
#pragma unroll
    for (int o = 0; o < 45; o++) {
        float a = sb[o];
#pragma unroll
        for (int q = 0; q < 8; q++) {
            float4 w4 = *reinterpret_cast<const float4*>(&sw[o * 32 + q * 4]);
            a = fmaf(hx[q * 4 + 0], w4.x, a);
            a = fmaf(hx[q * 4 + 1], w4.y, a);
            a = fmaf(hx[q * 4 + 2], w4.z, a);
            a = fmaf(hx[q * 4 + 3], w4.w, a);
        }
        op[o] = a;
    }
}

// ---------------------------------------------------------------------------
extern "C" void kernel_launch(void* const* d_in, const int* in_sizes, int n_in,
                              void* d_out, int out_size) {
    int off = (n_in >= 14) ? 1 : 0;
    const int*   data    = (const int*)d_in[0];
    const int*   lengths = (const int*)d_in[1 + off];
    const float* emb     = (const float*)d_in[2 + off];
    const float* h0      = (const float*)d_in[3 + off];
    const float* c0      = (const float*)d_in[4 + off];
    const float* w_ih_f  = (const float*)d_in[5 + off];
    const float* w_hh_f  = (const float*)d_in[6 + off];
    const float* b_f     = (const float*)d_in[7 + off];
    const float* w_ih_b  = (const float*)d_in[8 + off];
    const float* w_hh_b  = (const float*)d_in[9 + off];
    const float* b_b     = (const float*)d_in[10 + off];
    const float* lin_w   = (const float*)d_in[11 + off];
    const float* lin_b   = (const float*)d_in[12 + off];
    float* out = (float*)d_out;

    gates_kernel<<<dim3(TT / TCH, BB), 128>>>(data, lengths, emb, w_ih_f, b_f, w_ih_b, b_b);
    lstm_rec_kernel<<<2 * BB, 32>>>(h0, c0, w_hh_f, w_hh_b, lengths);
    out_kernel<<<(BB * TT + 127) / 128, 128>>>(lin_w, lin_b, lengths, out);
}

// round 4
// speedup vs baseline: 2.7043x; 1.0717x over previous
#include <cuda_runtime.h>
#include <cstdint>

#define BB 64
#define TT 4096
#define HH 15
#define EE 15
#define GG 60   /* 4*H */
#define TCH 32
#define UU 8    /* prefetch depth (steps) in the recurrence */

// Gate preacts per (t,b): 64 floats = 32 float2 slots.
// slot [grp*16 + j] holds (i_j,f_j) for grp=0, (g_j,o_j) for grp=1.
// j==15 slots never written -> stay zero (device globals are zero-initialized).
// Padded by 2*UU timesteps for deep prefetch over-reads.
__device__ float2 g_xgf2[(size_t)(TT + 2 * UU) * BB * 32];
__device__ float2 g_xgb2[(size_t)(TT + 2 * UU) * BB * 32];
// Hidden states, [b][j][t] layout (t-contiguous for batched STG.128).
// Backward stored in step-time (reversed at read).
__device__ float g_hsf[(size_t)BB * 16 * TT];
__device__ float g_hsbr[(size_t)BB * 16 * TT];

typedef unsigned long long ull;

__device__ __forceinline__ ull pack2(float lo, float hi) {
    ull r; asm("mov.b64 %0, {%1,%2};" : "=l"(r) : "f"(lo), "f"(hi)); return r;
}
__device__ __forceinline__ void unpack2(float& lo, float& hi, ull v) {
    asm("mov.b64 {%0,%1}, %2;" : "=f"(lo), "=f"(hi) : "l"(v));
}
__device__ __forceinline__ ull fma2(ull a, ull b, ull c) {
    ull d; asm("fma.rn.f32x2 %0, %1, %2, %3;" : "=l"(d) : "l"(a), "l"(b), "l"(c)); return d;
}
__device__ __forceinline__ ull add2(ull a, ull b) {
    ull d; asm("add.rn.f32x2 %0, %1, %2;" : "=l"(d) : "l"(a), "l"(b)); return d;
}
__device__ __forceinline__ float tanh_t(float x) {
    float t; asm("tanh.approx.f32 %0, %1;" : "=f"(t) : "f"(x)); return t;
}

// ---------------------------------------------------------------------------
// Kernel A: embedding gather + x @ W_ih^T + b -> paired-gate float2 layout.
// ---------------------------------------------------------------------------
__global__ void gates_kernel(const int* __restrict__ data,
                             const int* __restrict__ lengths,
                             const float* __restrict__ emb,
                             const float* __restrict__ w_ih_f,
                             const float* __restrict__ b_f,
                             const float* __restrict__ w_ih_b,
                             const float* __restrict__ b_b) {
    __shared__ int tok[2][TCH];
    __shared__ float xs[2][TCH][16];

    const int b   = blockIdx.y;
    const int t0  = blockIdx.x * TCH;
    const int tid = threadIdx.x;
    const int L   = lengths[b];

    if (tid < 2 * TCH) {
        int d  = tid / TCH, tl = tid % TCH;
        int tg = t0 + tl;
        int src = (d == 0) ? tg : min(max(L - 1 - tg, 0), TT - 1);
        tok[d][tl] = data[b * TT + src];
    }
    __syncthreads();
    for (int i = tid; i < 2 * TCH * EE; i += blockDim.x) {
        int e  = i % EE;
        int tl = (i / EE) % TCH;
        int d  = i / (EE * TCH);
        xs[d][tl][e] = emb[(size_t)tok[d][tl] * EE + e];
    }
    __syncthreads();

    if (tid < 2 * GG) {
        const int d    = tid / GG;
        const int g    = tid % GG;
        const int gate = g / HH;        // 0..3 = i,f,g,o
        const int j    = g % HH;
        const int grp  = gate >> 1;
        const int s    = gate & 1;
        const float* w = d ? w_ih_b : w_ih_f;
        const float bias = (d ? b_b : b_f)[g];
        float wr[EE];
#pragma unroll
        for (int k = 0; k < EE; k++) wr[k] = w[g * EE + k];
        float* out = (float*)(d ? g_xgb2 : g_xgf2);
#pragma unroll 4
        for (int tl = 0; tl < TCH; tl++) {
            float a = bias;
#pragma unroll
            for (int k = 0; k < EE; k++) a = fmaf(xs[d][tl][k], wr[k], a);
            out[(((size_t)(t0 + tl) * BB + b) * 32 + grp * 16 + j) * 2 + s] = a;
        }
    }
}

// ---------------------------------------------------------------------------
// Kernel B: LSTM recurrence. One warp per (dir, batch).
// Lanes 0-15: gates {i,f} of unit jj; lanes 16-31: gates {g,o} of unit jj
// (same instruction slots, lane-dependent weights). k-pair packed f32x2 dots,
// uniform parametrized activations, 2-shfl butterfly exchange, batched stores.
// ---------------------------------------------------------------------------
__global__ void __launch_bounds__(32, 1)
lstm_rec_kernel(const float* __restrict__ h0,
                const float* __restrict__ c0,
                const float* __restrict__ w_hh_f,
                const float* __restrict__ w_hh_b,
                const int* __restrict__ lengths) {
    const int b    = blockIdx.x & (BB - 1);
    const int dir  = blockIdx.x >> 6;
    const int lane = threadIdx.x;
    const int grp  = lane >> 4;        // 0: {i,f}, 1: {g,o}
    const int jj   = lane & 15;        // unit (15 = zero-padding lane)
    const int jp   = (jj < HH) ? jj : 0;

    const float*  whh = dir ? w_hh_b : w_hh_f;
    const float2* xg  = dir ? g_xgb2 : g_xgf2;
    float*        hso = (dir ? g_hsbr : g_hsf) + ((size_t)b * 16 + jj) * TT;
    const int L = lengths[b];

    // k-pair packed recurrent weights for this lane's two gates.
    const int rowA = (grp ? 2 * HH : 0) + jp;   // i or g
    const int rowB = (grp ? 3 * HH : HH) + jp;  // f or o
    ull wA[8], wB[8];
#pragma unroll
    for (int p = 0; p < 8; p++) {
        float a0 = whh[rowA * HH + 2 * p];
        float a1 = (2 * p + 1 < HH) ? whh[rowA * HH + 2 * p + 1] : 0.0f;
        float b0 = whh[rowB * HH + 2 * p];
        float b1 = (2 * p + 1 < HH) ? whh[rowB * HH + 2 * p + 1] : 0.0f;
        if (jj == 15) { a0 = a1 = b0 = b1 = 0.0f; }
        wA[p] = pack2(a0, a1);
        wB[p] = pack2(b0, b1);
    }
    // Activation params: grp0 gateA = sigmoid(i), grp1 gateA = tanh(g).
    const float sclA = grp ? 1.0f : 0.5f;
    const float mulA = grp ? 1.0f : 0.5f;
    const float addA = grp ? 0.0f : 0.5f;

    float hj = h0[((size_t)dir * BB + b) * HH + jp];
    float c  = c0[((size_t)dir * BB + b) * HH + jp];
    if (jj == 15) hj = 0.0f;

    // Initial h pairs {h_2p, h_2p+1} (lane 15 sources 0).
    ull hp[8];
    {
        float hsel = (jj == 15) ? 0.0f : hj;
#pragma unroll
        for (int p = 0; p < 8; p++)
            hp[p] = pack2(__shfl_sync(0xffffffffu, hsel, 2 * p),
                          __shfl_sync(0xffffffffu, hsel, 2 * p + 1));
    }

    const size_t stride = (size_t)BB * 32;
    const float2* xgp = xg + (size_t)b * 32 + grp * 16 + jj;

    float2 pf[UU];
#pragma unroll
    for (int u = 0; u < UU; u++) pf[u] = xgp[(size_t)u * stride];

    float hb0 = 0, hb1 = 0, hb2 = 0;

    for (int t = 0; t < L; t += UU) {
#pragma unroll
        for (int u = 0; u < UU; u++) {
            float2 pv = pf[u];
            pf[u] = xgp[(size_t)(t + u + UU) * stride];  // padding-safe refill

            ull A0 = pack2(pv.x, 0.0f), A1 = pack2(0.0f, 0.0f);
            ull B0 = pack2(pv.y, 0.0f), B1 = pack2(0.0f, 0.0f);
#pragma unroll
            for (int p = 0; p < 4; p++) {
                A0 = fma2(hp[p], wA[p], A0);
                B0 = fma2(hp[p], wB[p], B0);
            }
#pragma unroll
            for (int p = 4; p < 8; p++) {
                A1 = fma2(hp[p], wA[p], A1);
                B1 = fma2(hp[p], wB[p], B1);
            }
            ull As = add2(A0, A1), Bs = add2(B0, B1);
            float al, ah, bl, bh;
            unpack2(al, ah, As); unpack2(bl, bh, Bs);
            float aA = al + ah, aB = bl + bh;

            // gateA: sigmoid (grp0) / tanh (grp1); gateB: sigmoid (both).
            float rA = fmaf(mulA, tanh_t(aA * sclA), addA);
            float rB = fmaf(0.5f, tanh_t(aB * 0.5f), 0.5f);

            float xA = __shfl_xor_sync(0xffffffffu, rA, 16);
            float xB = __shfl_xor_sync(0xffffffffu, rB, 16);
            // grp0 view: rA=i, rB=f, xA=g, xB=o. (grp1 computes bounded garbage.)
            c  = fmaf(rB, c, rA * xA);
            hj = xB * tanh_t(c);

            float hsel = (jj == 15) ? 0.0f : hj;
#pragma unroll
            for (int p = 0; p < 8; p++)
                hp[p] = pack2(__shfl_sync(0xffffffffu, hsel, 2 * p),
                              __shfl_sync(0xffffffffu, hsel, 2 * p + 1));

            // Batched store every 4 steps (over-store past L is never read).
            if ((u & 3) == 0) hb0 = hj;
            else if ((u & 3) == 1) hb1 = hj;
            else if ((u & 3) == 2) hb2 = hj;
            else if (lane < HH)
                *(float4*)(hso + (t + u - 3)) = make_float4(hb0, hb1, hb2, hj);
        }
    }
}

// ---------------------------------------------------------------------------
// Kernel C: out[b,t,:] = valid ? [hf|hb] @ lin_w^T + lin_b : lin_b
// Reads hsf at t, hsbr at L-1-t (both [b][j][t] layout, coalesced per warp).
// ---------------------------------------------------------------------------
__global__ void out_kernel(const float* __restrict__ lin_w,
                           const float* __restrict__ lin_b,
                           const int* __restrict__ lengths,
                           float* __restrict__ out) {
    __shared__ __align__(16) float sw[45 * 32];
    __shared__ float sb[45];
    const int tid = threadIdx.x;
    for (int i = tid; i < 45 * 32; i += blockDim.x) {
        int o = i >> 5, k = i & 31;
        sw[i] = (k < 30) ? lin_w[o * 30 + k] : 0.0f;
    }
    if (tid < 45) sb[tid] = lin_b[tid];
    __syncthreads();

    const int idx = blockIdx.x * blockDim.x + tid;
    if (idx >= BB * TT) return;
    const int b = idx >> 12;
    const int t = idx & (TT - 1);
    const int L = lengths[b];

    float hx[32];
#pragma unroll
    for (int k = 0; k < 32; k++) hx[k] = 0.0f;
    if (t < L) {
        const int rev = L - 1 - t;
#pragma unroll
        for (int k = 0; k < HH; k++) {
            hx[k]      = g_hsf[((size_t)b * 16 + k) * TT + t];
            hx[15 + k] = g_hsbr[((size_t)b * 16 + k) * TT + rev];
        }
    }

    float* op = out + (size_t)idx * 45;
#pragma unroll
    for (int o = 0; o < 45; o++) {
        float a = sb[o];
#pragma unroll
        for (int q = 0; q < 8; q++) {
            float4 w4 = *reinterpret_cast<const float4*>(&sw[o * 32 + q * 4]);
            a = fmaf(hx[q * 4 + 0], w4.x, a);
            a = fmaf(hx[q * 4 + 1], w4.y, a);
            a = fmaf(hx[q * 4 + 2], w4.z, a);
            a = fmaf(hx[q * 4 + 3], w4.w, a);
        }
        op[o] = a;
    }
}

// ---------------------------------------------------------------------------
extern "C" void kernel_launch(void* const* d_in, const int* in_sizes, int n_in,
                              void* d_out, int out_size) {
    int off = (n_in >= 14) ? 1 : 0;
    const int*   data    = (const int*)d_in[0];
    const int*   lengths = (const int*)d_in[1 + off];
    const float* emb     = (const float*)d_in[2 + off];
    const float* h0      = (const float*)d_in[3 + off];
    const float* c0      = (const float*)d_in[4 + off];
    const float* w_ih_f  = (const float*)d_in[5 + off];
    const float* w_hh_f  = (const float*)d_in[6 + off];
    const float* b_f     = (const float*)d_in[7 + off];
    const float* w_ih_b  = (const float*)d_in[8 + off];
    const float* w_hh_b  = (const float*)d_in[9 + off];
    const float* b_b     = (const float*)d_in[10 + off];
    const float* lin_w   = (const float*)d_in[11 + off];
    const float* lin_b   = (const float*)d_in[12 + off];
    float* out = (float*)d_out;

    gates_kernel<<<dim3(TT / TCH, BB), 128>>>(data, lengths, emb, w_ih_f, b_f, w_ih_b, b_b);
    lstm_rec_kernel<<<2 * BB, 32>>>(h0, c0, w_hh_f, w_hh_b, lengths);
    out_kernel<<<(BB * TT + 127) / 128, 128>>>(lin_w, lin_b, lengths, out);
}